// round 2
// baseline (speedup 1.0000x reference)
#include <cuda_runtime.h>

// Problem constants
static constexpr int B_DIM = 256;
static constexpr int N_DIM = 65536;
static constexpr int BN    = B_DIM * N_DIM;          // 16,777,216
static constexpr int BN4   = BN / 4;                 // 4,194,304 float4 per tensor
static constexpr int N4    = N_DIM / 4;              // 16,384 float4 in row 0

// k_main geometry: 256 threads * ILP 4 = 1024 float4 per block
static constexpr int MAIN_THREADS = 256;
static constexpr int MAIN_ILP     = 4;
static constexpr int MAIN_CHUNK   = MAIN_THREADS * MAIN_ILP;     // 1024
static constexpr int MAIN_BLOCKS  = BN4 / MAIN_CHUNK;            // 4096
static constexpr int ROW0_BLOCKS  = N4 / MAIN_CHUNK;             // 16 (exact)

// reduce geometry: 32 blocks * 512 threads * 1 float4 = 16384 = N4 (exact)
static constexpr int RED_BLOCKS  = 32;
static constexpr int RED_THREADS = 512;

// LIF-AdEx parameters (defaults from reference)
#define TAU_SYN_INV   0.5f
#define TAU_MEM_INV   0.5f
#define V_TH          1.0f
#define V_PEAK        30.0f
#define INHIBITION    (-5.0f)

// Per-block winner keys, written UNCONDITIONALLY every replay (stale values
// from the previous replay are always overwritten -> no init kernel needed).
// Key: upper 32 bits = float bits of v_before (positive when spiked, so raw
// bits are order-preserving); lower 32 bits = 0xFFFFFFFF - col so max picks
// the LOWEST column on ties (jnp.argmax semantics). key == 0 <=> no spike.
__device__ unsigned long long g_partial[RED_BLOCKS];

// Shared elementwise step — arithmetically identical in both kernels so the
// row-0 spike decision agrees between the reduction and the main pass.
__device__ __forceinline__ void lif_step(float x, float v, float i, float w,
                                         float& z, float& v_out, float& i_new,
                                         float& w_new, float& v_before) {
    i_new = fmaf(TAU_SYN_INV, x - i, i);                 // i + 0.5*(x - i)
    float e = __expf(v - V_TH);                          // delta_t*exp((v-v_th)/delta_t)
    float s = e + i_new - w - v;                         // -(v-v_rest) + e + i_new - w
    float vn = fmaf(TAU_MEM_INV, s, v);                  // v + 0.5*s
    w_new = 0.5f * w;                                    // a_param = 0
    v_before = vn;
    bool spike = (vn >= V_PEAK);
    z = spike ? 1.0f : 0.0f;
    v_out = spike ? 0.0f : vn;                           // v_reset=0, b_param=0
}

__device__ __forceinline__ unsigned long long
umax64(unsigned long long a, unsigned long long b) { return a > b ? a : b; }

// Stage 1: per-block winner over row 0 (reads only 1 MB — negligible).
__global__ void __launch_bounds__(RED_THREADS)
k_row0_reduce(const float4* __restrict__ x,
              const float4* __restrict__ v,
              const float4* __restrict__ i,
              const float4* __restrict__ w) {
    int t = blockIdx.x * RED_THREADS + threadIdx.x;      // 0 .. N4-1 (exact)

    float4 xf = __ldcs(&x[t]), vf = __ldcs(&v[t]);
    float4 if4 = __ldcs(&i[t]), wf = __ldcs(&w[t]);
    float xs[4] = {xf.x, xf.y, xf.z, xf.w};
    float vs[4] = {vf.x, vf.y, vf.z, vf.w};
    float is[4] = {if4.x, if4.y, if4.z, if4.w};
    float ws[4] = {wf.x, wf.y, wf.z, wf.w};

    unsigned long long best = 0ULL;
#pragma unroll
    for (int k = 0; k < 4; k++) {
        float z, vo, in, wn, vb;
        lif_step(xs[k], vs[k], is[k], ws[k], z, vo, in, wn, vb);
        if (vb >= V_PEAK) {
            unsigned col = (unsigned)(t * 4 + k);
            unsigned long long key =
                ((unsigned long long)__float_as_uint(vb) << 32) |
                (unsigned long long)(0xFFFFFFFFu - col);
            best = umax64(best, key);
        }
    }

    // warp reduce
#pragma unroll
    for (int o = 16; o > 0; o >>= 1)
        best = umax64(best, __shfl_down_sync(0xFFFFFFFFu, best, o));

    // cross-warp reduce via smem (16 warps)
    __shared__ unsigned long long s_warp[RED_THREADS / 32];
    int wid = threadIdx.x >> 5, lid = threadIdx.x & 31;
    if (lid == 0) s_warp[wid] = best;
    __syncthreads();
    if (wid == 0) {
        best = (lid < RED_THREADS / 32) ? s_warp[lid] : 0ULL;
#pragma unroll
        for (int o = 8; o > 0; o >>= 1)
            best = umax64(best, __shfl_down_sync(0xFFFFFFFFu, best, o));
        if (lid == 0) g_partial[blockIdx.x] = best;      // unconditional write
    }
}

// Stage 2: full elementwise pass, ILP=4 float4 per thread. Row-0 blocks
// reduce the 32 partials themselves (no init/atomic needed).
__global__ void __launch_bounds__(MAIN_THREADS)
k_main(const float4* __restrict__ x,
       const float4* __restrict__ v,
       const float4* __restrict__ i,
       const float4* __restrict__ w,
       float4* __restrict__ out) {
    const int base = blockIdx.x * MAIN_CHUNK + threadIdx.x;
    const bool row0 = (blockIdx.x < ROW0_BLOCKS);        // whole block in row 0

    __shared__ unsigned long long s_key;
    if (row0) {
        if (threadIdx.x < 32) {
            unsigned long long kk = g_partial[threadIdx.x];  // RED_BLOCKS == 32
#pragma unroll
            for (int o = 16; o > 0; o >>= 1)
                kk = umax64(kk, __shfl_down_sync(0xFFFFFFFFu, kk, o));
            if (threadIdx.x == 0) s_key = kk;
        }
        __syncthreads();
    }

#pragma unroll
    for (int c = 0; c < MAIN_ILP; c++) {
        const int t = base + c * MAIN_THREADS;           // coalesced within warp

        float4 xf = __ldcs(&x[t]), vf = __ldcs(&v[t]);
        float4 if4 = __ldcs(&i[t]), wf = __ldcs(&w[t]);
        float xs[4] = {xf.x, xf.y, xf.z, xf.w};
        float vs[4] = {vf.x, vf.y, vf.z, vf.w};
        float is[4] = {if4.x, if4.y, if4.z, if4.w};
        float ws[4] = {wf.x, wf.y, wf.z, wf.w};

        float zo[4], vo[4], io[4], wo[4];
#pragma unroll
        for (int k = 0; k < 4; k++) {
            float vb;
            lif_step(xs[k], vs[k], is[k], ws[k], zo[k], vo[k], io[k], wo[k], vb);
        }

        if (row0) {
            unsigned long long key = s_key;
            if (key != 0ULL) {                           // any_spike0
                unsigned winner = 0xFFFFFFFFu - (unsigned)(key & 0xFFFFFFFFull);
                int col = t * 4;
#pragma unroll
                for (int k = 0; k < 4; k++) {
                    if ((unsigned)(col + k) != winner) { // inhibit all but winner
                        vo[k] = INHIBITION;
                        wo[k] = 0.0f;
                    }
                }
            }
        }

        __stcs(&out[t],           make_float4(zo[0], zo[1], zo[2], zo[3]));
        __stcs(&out[BN4 + t],     make_float4(vo[0], vo[1], vo[2], vo[3]));
        __stcs(&out[2 * BN4 + t], make_float4(io[0], io[1], io[2], io[3]));
        __stcs(&out[3 * BN4 + t], make_float4(wo[0], wo[1], wo[2], wo[3]));
    }
}

extern "C" void kernel_launch(void* const* d_in, const int* in_sizes, int n_in,
                              void* d_out, int out_size) {
    const float4* x = (const float4*)d_in[0];
    const float4* v = (const float4*)d_in[1];
    const float4* i = (const float4*)d_in[2];
    const float4* w = (const float4*)d_in[3];
    float4* out = (float4*)d_out;

    k_row0_reduce<<<RED_BLOCKS, RED_THREADS>>>(x, v, i, w);
    k_main<<<MAIN_BLOCKS, MAIN_THREADS>>>(x, v, i, w, out);
}